// round 4
// baseline (speedup 1.0000x reference)
#include <cuda_runtime.h>

// VectorQuantizer: argmax_k ( W[k] . z ), emit W[argmax], index, commit loss.
// W: 131072 x 1024 f32 (512 MiB) -> pure HBM stream; floor ~65us @ 8 TB/s.
// SINGLE persistent kernel: streaming argmax at 4 CTA/SM (regs capped 64),
// per-block slots, last-block ticket runs the epilogue. No init, no 2nd launch.

#define VQ_DIM   1024
#define VQ_ROWS  131072
#define ARG_BLOCKS  592          // 148 SMs x 4 CTAs -> single wave, persistent
#define ARG_THREADS 256
#define N_WARPS_TOT (ARG_BLOCKS * ARG_THREADS / 32)

// Per-block packed (float_key(dot) << 32 | ~row). Overwritten every launch.
__device__ unsigned long long g_block_best[ARG_BLOCKS];
__device__ unsigned int g_done_count = 0;   // reset by last block each run

// Monotonic float -> uint key: preserves ordering for all finite floats.
__device__ __forceinline__ unsigned float_key(float f) {
    unsigned u = __float_as_uint(f);
    return (u & 0x80000000u) ? ~u : (u | 0x80000000u);
}

__device__ __forceinline__ unsigned long long warp_max_u64(unsigned long long v) {
    #pragma unroll
    for (int off = 16; off; off >>= 1) {
        unsigned long long o = __shfl_xor_sync(0xffffffffu, v, off);
        if (o > v) v = o;
    }
    return v;
}

__global__ __launch_bounds__(ARG_THREADS, 4)   // cap regs at 64 -> 32 warps/SM
void vq_kernel(const float* __restrict__ z, const float* __restrict__ W,
               float* __restrict__ out, int out_size) {
    __shared__ float zs[VQ_DIM];
    __shared__ unsigned long long red64[ARG_THREADS / 32];
    __shared__ float redf[ARG_THREADS / 32];
    __shared__ bool is_last;

    const int tid  = threadIdx.x;
    const int lane = tid & 31;
    const int wwid = tid >> 5;

    // Stage z into shared (4 KB), vectorized.
    const float4* z4 = (const float4*)z;
    float4* zs4 = (float4*)zs;
    for (int i = tid; i < VQ_DIM / 4; i += ARG_THREADS)
        zs4[i] = z4[i];
    if (tid == 0) is_last = false;
    __syncthreads();

    const int gwarp = (blockIdx.x * ARG_THREADS + tid) >> 5;

    unsigned long long best = 0ULL;

    for (int row = gwarp; row < VQ_ROWS; row += N_WARPS_TOT) {
        const float4* wr = (const float4*)(W + (size_t)row * VQ_DIM);
        // All 8 LDG.128s issued up front (max per-warp MLP), streaming hint.
        float4 w0 = __ldcs(wr + lane +   0);
        float4 w1 = __ldcs(wr + lane +  32);
        float4 w2 = __ldcs(wr + lane +  64);
        float4 w3 = __ldcs(wr + lane +  96);
        float4 w4 = __ldcs(wr + lane + 128);
        float4 w5 = __ldcs(wr + lane + 160);
        float4 w6 = __ldcs(wr + lane + 192);
        float4 w7 = __ldcs(wr + lane + 224);
        float a0, a1, a2, a3;
        { float4 p = zs4[lane +   0]; a0  = w0.x*p.x + w0.y*p.y + w0.z*p.z + w0.w*p.w; }
        { float4 p = zs4[lane +  32]; a1  = w1.x*p.x + w1.y*p.y + w1.z*p.z + w1.w*p.w; }
        { float4 p = zs4[lane +  64]; a2  = w2.x*p.x + w2.y*p.y + w2.z*p.z + w2.w*p.w; }
        { float4 p = zs4[lane +  96]; a3  = w3.x*p.x + w3.y*p.y + w3.z*p.z + w3.w*p.w; }
        { float4 p = zs4[lane + 128]; a0 += w4.x*p.x + w4.y*p.y + w4.z*p.z + w4.w*p.w; }
        { float4 p = zs4[lane + 160]; a1 += w5.x*p.x + w5.y*p.y + w5.z*p.z + w5.w*p.w; }
        { float4 p = zs4[lane + 192]; a2 += w6.x*p.x + w6.y*p.y + w6.z*p.z + w6.w*p.w; }
        { float4 p = zs4[lane + 224]; a3 += w7.x*p.x + w7.y*p.y + w7.z*p.z + w7.w*p.w; }
        float dot = (a0 + a1) + (a2 + a3);

        #pragma unroll
        for (int off = 16; off; off >>= 1)
            dot += __shfl_xor_sync(0xffffffffu, dot, off);

        // ~row in low bits: ties resolve to SMALLEST row (jnp.argmax semantics).
        unsigned long long p =
            ((unsigned long long)float_key(dot) << 32) |
            (unsigned long long)(0xFFFFFFFFu - (unsigned)row);
        if (p > best) best = p;
    }

    // One value per warp -> 8-entry smem max -> slot store.
    if (lane == 0) red64[wwid] = best;
    __syncthreads();
    if (tid == 0) {
        unsigned long long v = red64[0];
        #pragma unroll
        for (int i = 1; i < ARG_THREADS / 32; i++)
            if (red64[i] > v) v = red64[i];
        g_block_best[blockIdx.x] = v;
        __threadfence();
        unsigned t = atomicAdd(&g_done_count, 1u);
        is_last = (t == ARG_BLOCKS - 1);
    }
    __syncthreads();
    if (!is_last) return;

    // ---- Epilogue: only the last-arriving block executes this (runs once). ----
    __threadfence();  // acquire: make all blocks' slot stores visible

    unsigned long long b = 0ULL;
    for (int i = tid; i < ARG_BLOCKS; i += ARG_THREADS) {
        unsigned long long v = g_block_best[i];
        if (v > b) b = v;
    }
    b = warp_max_u64(b);
    if (lane == 0) red64[wwid] = b;
    __syncthreads();
    if (tid == 0) {
        unsigned long long v = red64[0];
        #pragma unroll
        for (int i = 1; i < ARG_THREADS / 32; i++)
            if (red64[i] > v) v = red64[i];
        red64[0] = v;
    }
    __syncthreads();
    const unsigned row = 0xFFFFFFFFu - (unsigned)(red64[0] & 0xFFFFFFFFull);
    const float* q = W + (size_t)row * VQ_DIM;

    float s = 0.f;
    for (int i = tid; i < VQ_DIM; i += ARG_THREADS) {
        float qi = q[i];
        float d  = zs[i] - qi;
        s += d * d;
        if (i < out_size) out[i] = qi;   // quantized_st == quantized numerically
    }
    #pragma unroll
    for (int off = 16; off; off >>= 1)
        s += __shfl_xor_sync(0xffffffffu, s, off);
    if (lane == 0) redf[wwid] = s;
    __syncthreads();
    if (tid == 0) {
        float t = 0.f;
        #pragma unroll
        for (int i = 0; i < ARG_THREADS / 32; i++) t += redf[i];
        if (out_size >= VQ_DIM + 1) out[VQ_DIM]     = (float)row;
        if (out_size >= VQ_DIM + 2) out[VQ_DIM + 1] = 0.25f * t / (float)VQ_DIM;
        g_done_count = 0;  // reset for next graph replay
    }
}

extern "C" void kernel_launch(void* const* d_in, const int* in_sizes, int n_in,
                              void* d_out, int out_size) {
    const float* z = (const float*)d_in[0];
    const float* W = (const float*)d_in[1];
    if (n_in >= 2 && in_sizes[0] != VQ_DIM && in_sizes[1] == VQ_DIM) {
        z = (const float*)d_in[1];
        W = (const float*)d_in[0];
    }
    vq_kernel<<<ARG_BLOCKS, ARG_THREADS>>>(z, W, (float*)d_out, out_size);
}

// round 5
// speedup vs baseline: 1.0117x; 1.0117x over previous
#include <cuda_runtime.h>

// VectorQuantizer: argmax_k ( W[k] . z ), emit W[argmax], index, commit loss.
// W: 131072 x 1024 f32 (512 MiB) -> pure HBM stream; floor ~65us @ 8 TB/s.
// Two launches (fusion regressed twice: epilogue code costs streaming occupancy).
// Argmax kernel: reg-lean body (4-deep load batches) at 6 CTA/SM -> 75% occ.

#define VQ_DIM   1024
#define VQ_ROWS  131072
#define ARG_CTAS_PER_SM 6
#define ARG_BLOCKS  (148 * ARG_CTAS_PER_SM)   // 888: single persistent wave
#define ARG_THREADS 256
#define N_WARPS_TOT (ARG_BLOCKS * ARG_THREADS / 32)

// Per-block packed (float_key(dot) << 32 | ~row). Overwritten every launch.
__device__ unsigned long long g_block_best[ARG_BLOCKS];

// Monotonic float -> uint key: preserves ordering for all finite floats.
__device__ __forceinline__ unsigned float_key(float f) {
    unsigned u = __float_as_uint(f);
    return (u & 0x80000000u) ? ~u : (u | 0x80000000u);
}

__global__ __launch_bounds__(ARG_THREADS, ARG_CTAS_PER_SM)  // cap ~42 regs
void vq_argmax_kernel(const float* __restrict__ z, const float* __restrict__ W) {
    __shared__ float zs[VQ_DIM];
    __shared__ unsigned long long red64[ARG_THREADS / 32];

    const int tid  = threadIdx.x;
    const int lane = tid & 31;
    const int wwid = tid >> 5;

    // Stage z into shared (4 KB), vectorized.
    const float4* z4 = (const float4*)z;
    float4* zs4 = (float4*)zs;
    for (int i = tid; i < VQ_DIM / 4; i += ARG_THREADS)
        zs4[i] = z4[i];
    __syncthreads();

    const int gwarp = (blockIdx.x * ARG_THREADS + tid) >> 5;

    unsigned long long best = 0ULL;

    for (int row = gwarp; row < VQ_ROWS; row += N_WARPS_TOT) {
        const float4* wr = (const float4*)(W + (size_t)row * VQ_DIM);
        // Two 4-deep load batches: 16 data regs live instead of 32, so the
        // kernel fits 6 CTAs/SM. 4 LDG.128/warp x 48 warps/SM still gives
        // ~96KB outstanding per SM -- well above the latency-BW product.
        float a0, a1, a2, a3;
        {
            float4 w0 = __ldcs(wr + lane +   0);
            float4 w1 = __ldcs(wr + lane +  32);
            float4 w2 = __ldcs(wr + lane +  64);
            float4 w3 = __ldcs(wr + lane +  96);
            float4 p0 = zs4[lane +   0];
            float4 p1 = zs4[lane +  32];
            float4 p2 = zs4[lane +  64];
            float4 p3 = zs4[lane +  96];
            a0 = w0.x*p0.x + w0.y*p0.y + w0.z*p0.z + w0.w*p0.w;
            a1 = w1.x*p1.x + w1.y*p1.y + w1.z*p1.z + w1.w*p1.w;
            a2 = w2.x*p2.x + w2.y*p2.y + w2.z*p2.z + w2.w*p2.w;
            a3 = w3.x*p3.x + w3.y*p3.y + w3.z*p3.z + w3.w*p3.w;
        }
        {
            float4 w0 = __ldcs(wr + lane + 128);
            float4 w1 = __ldcs(wr + lane + 160);
            float4 w2 = __ldcs(wr + lane + 192);
            float4 w3 = __ldcs(wr + lane + 224);
            float4 p0 = zs4[lane + 128];
            float4 p1 = zs4[lane + 160];
            float4 p2 = zs4[lane + 192];
            float4 p3 = zs4[lane + 224];
            a0 += w0.x*p0.x + w0.y*p0.y + w0.z*p0.z + w0.w*p0.w;
            a1 += w1.x*p1.x + w1.y*p1.y + w1.z*p1.z + w1.w*p1.w;
            a2 += w2.x*p2.x + w2.y*p2.y + w2.z*p2.z + w2.w*p2.w;
            a3 += w3.x*p3.x + w3.y*p3.y + w3.z*p3.z + w3.w*p3.w;
        }
        float dot = (a0 + a1) + (a2 + a3);

        #pragma unroll
        for (int off = 16; off; off >>= 1)
            dot += __shfl_xor_sync(0xffffffffu, dot, off);

        // ~row in low bits: ties resolve to SMALLEST row (jnp.argmax semantics).
        unsigned long long p =
            ((unsigned long long)float_key(dot) << 32) |
            (unsigned long long)(0xFFFFFFFFu - (unsigned)row);
        if (p > best) best = p;
    }

    // One value per warp -> 8-entry smem max -> slot store (no atomics).
    if (lane == 0) red64[wwid] = best;
    __syncthreads();
    if (tid == 0) {
        unsigned long long v = red64[0];
        #pragma unroll
        for (int i = 1; i < ARG_THREADS / 32; i++)
            if (red64[i] > v) v = red64[i];
        g_block_best[blockIdx.x] = v;
    }
}

__global__ __launch_bounds__(256)
void vq_finalize_kernel(const float* __restrict__ z,
                        const float* __restrict__ W,
                        float* __restrict__ out, int out_size) {
    __shared__ unsigned long long red64[256];
    __shared__ float redf[256];
    const int tid = threadIdx.x;

    unsigned long long b = 0ULL;
    for (int i = tid; i < ARG_BLOCKS; i += 256) {
        unsigned long long v = g_block_best[i];
        if (v > b) b = v;
    }
    red64[tid] = b;
    __syncthreads();
    #pragma unroll
    for (int o = 128; o; o >>= 1) {
        if (tid < o) { unsigned long long v = red64[tid + o]; if (v > red64[tid]) red64[tid] = v; }
        __syncthreads();
    }
    const unsigned row = 0xFFFFFFFFu - (unsigned)(red64[0] & 0xFFFFFFFFull);
    const float* q = W + (size_t)row * VQ_DIM;

    float s = 0.f;
    for (int i = tid; i < VQ_DIM; i += 256) {
        float qi = q[i];
        float d  = z[i] - qi;
        s += d * d;
        if (i < out_size) out[i] = qi;   // quantized_st == quantized numerically
    }
    redf[tid] = s;
    __syncthreads();
    #pragma unroll
    for (int o = 128; o; o >>= 1) {
        if (tid < o) redf[tid] += redf[tid + o];
        __syncthreads();
    }
    if (tid == 0) {
        if (out_size >= VQ_DIM + 1) out[VQ_DIM]     = (float)row;
        if (out_size >= VQ_DIM + 2) out[VQ_DIM + 1] = 0.25f * redf[0] / (float)VQ_DIM;
    }
}

extern "C" void kernel_launch(void* const* d_in, const int* in_sizes, int n_in,
                              void* d_out, int out_size) {
    const float* z = (const float*)d_in[0];
    const float* W = (const float*)d_in[1];
    if (n_in >= 2 && in_sizes[0] != VQ_DIM && in_sizes[1] == VQ_DIM) {
        z = (const float*)d_in[1];
        W = (const float*)d_in[0];
    }
    vq_argmax_kernel<<<ARG_BLOCKS, ARG_THREADS>>>(z, W);
    vq_finalize_kernel<<<1, 256>>>(z, W, (float*)d_out, out_size);
}

// round 6
// speedup vs baseline: 1.0253x; 1.0134x over previous
#include <cuda_runtime.h>

// VectorQuantizer: argmax_k ( W[k] . z ), emit W[argmax], index, commit loss.
// W: 131072 x 1024 f32 (512 MiB) -> pure HBM stream; floor ~65us @ 8 TB/s.
// Streaming argmax (R3 config: 8-deep LDG batch, 4 CTA/SM — measured fastest,
// ~7.4 TB/s) + finalize kernel overlapped via Programmatic Dependent Launch.

#define VQ_DIM   1024
#define VQ_ROWS  131072
#define ARG_BLOCKS  592          // 148 SMs x 4 CTAs -> single persistent wave
#define ARG_THREADS 256
#define N_WARPS_TOT (ARG_BLOCKS * ARG_THREADS / 32)
#define FIN_THREADS 512

// Per-block packed (float_key(dot) << 32 | ~row). Overwritten every launch.
__device__ unsigned long long g_block_best[ARG_BLOCKS];

// Monotonic float -> uint key: preserves ordering for all finite floats.
__device__ __forceinline__ unsigned float_key(float f) {
    unsigned u = __float_as_uint(f);
    return (u & 0x80000000u) ? ~u : (u | 0x80000000u);
}

__global__ __launch_bounds__(ARG_THREADS, 4)   // 32 warps/SM, regs <= 64
void vq_argmax_kernel(const float* __restrict__ z, const float* __restrict__ W) {
    __shared__ float zs[VQ_DIM];
    __shared__ unsigned long long red64[ARG_THREADS / 32];

    const int tid  = threadIdx.x;
    const int lane = tid & 31;
    const int wwid = tid >> 5;

    // Stage z into shared (4 KB), vectorized.
    const float4* z4 = (const float4*)z;
    float4* zs4 = (float4*)zs;
    for (int i = tid; i < VQ_DIM / 4; i += ARG_THREADS)
        zs4[i] = z4[i];
    __syncthreads();

    const int gwarp = (blockIdx.x * ARG_THREADS + tid) >> 5;

    unsigned long long best = 0ULL;

    for (int row = gwarp; row < VQ_ROWS; row += N_WARPS_TOT) {
        const float4* wr = (const float4*)(W + (size_t)row * VQ_DIM);
        // All 8 LDG.128s issued up front (max per-warp MLP), streaming hint.
        float4 w0 = __ldcs(wr + lane +   0);
        float4 w1 = __ldcs(wr + lane +  32);
        float4 w2 = __ldcs(wr + lane +  64);
        float4 w3 = __ldcs(wr + lane +  96);
        float4 w4 = __ldcs(wr + lane + 128);
        float4 w5 = __ldcs(wr + lane + 160);
        float4 w6 = __ldcs(wr + lane + 192);
        float4 w7 = __ldcs(wr + lane + 224);
        float a0, a1, a2, a3;
        { float4 p = zs4[lane +   0]; a0  = w0.x*p.x + w0.y*p.y + w0.z*p.z + w0.w*p.w; }
        { float4 p = zs4[lane +  32]; a1  = w1.x*p.x + w1.y*p.y + w1.z*p.z + w1.w*p.w; }
        { float4 p = zs4[lane +  64]; a2  = w2.x*p.x + w2.y*p.y + w2.z*p.z + w2.w*p.w; }
        { float4 p = zs4[lane +  96]; a3  = w3.x*p.x + w3.y*p.y + w3.z*p.z + w3.w*p.w; }
        { float4 p = zs4[lane + 128]; a0 += w4.x*p.x + w4.y*p.y + w4.z*p.z + w4.w*p.w; }
        { float4 p = zs4[lane + 160]; a1 += w5.x*p.x + w5.y*p.y + w5.z*p.z + w5.w*p.w; }
        { float4 p = zs4[lane + 192]; a2 += w6.x*p.x + w6.y*p.y + w6.z*p.z + w6.w*p.w; }
        { float4 p = zs4[lane + 224]; a3 += w7.x*p.x + w7.y*p.y + w7.z*p.z + w7.w*p.w; }
        float dot = (a0 + a1) + (a2 + a3);

        #pragma unroll
        for (int off = 16; off; off >>= 1)
            dot += __shfl_xor_sync(0xffffffffu, dot, off);

        // ~row in low bits: ties resolve to SMALLEST row (jnp.argmax semantics).
        unsigned long long p =
            ((unsigned long long)float_key(dot) << 32) |
            (unsigned long long)(0xFFFFFFFFu - (unsigned)row);
        if (p > best) best = p;
    }

    // One value per warp -> 8-entry smem max -> slot store (no atomics).
    if (lane == 0) red64[wwid] = best;
    __syncthreads();
    if (tid == 0) {
        unsigned long long v = red64[0];
        #pragma unroll
        for (int i = 1; i < ARG_THREADS / 32; i++)
            if (red64[i] > v) v = red64[i];
        g_block_best[blockIdx.x] = v;
        __threadfence();
        // PDL: let the finalize kernel launch as blocks drain.
        asm volatile("griddepcontrol.launch_dependents;");
    }
}

__global__ __launch_bounds__(FIN_THREADS)
void vq_finalize_kernel(const float* __restrict__ z,
                        const float* __restrict__ W,
                        float* __restrict__ out, int out_size) {
    __shared__ unsigned long long red64[FIN_THREADS / 32];
    __shared__ float redf[FIN_THREADS / 32];
    const int tid  = threadIdx.x;
    const int lane = tid & 31;
    const int wwid = tid >> 5;

    // Prefetch z (independent of the primary kernel) BEFORE the PDL wait so
    // this DRAM latency overlaps the argmax tail.
    float zv0 = z[tid];
    float zv1 = z[tid + FIN_THREADS];

    // Block until the primary grid completes; orders its slot stores.
    asm volatile("griddepcontrol.wait;" ::: "memory");

    // Scan the 592 slots (<=2 per thread).
    unsigned long long b = g_block_best[tid >= ARG_BLOCKS ? 0 : tid];
    if (tid + FIN_THREADS < ARG_BLOCKS) {
        unsigned long long v = g_block_best[tid + FIN_THREADS];
        if (v > b) b = v;
    }
    #pragma unroll
    for (int off = 16; off; off >>= 1) {
        unsigned long long o = __shfl_xor_sync(0xffffffffu, b, off);
        if (o > b) b = o;
    }
    if (lane == 0) red64[wwid] = b;
    __syncthreads();
    if (tid == 0) {
        unsigned long long v = red64[0];
        #pragma unroll
        for (int i = 1; i < FIN_THREADS / 32; i++)
            if (red64[i] > v) v = red64[i];
        red64[0] = v;
    }
    __syncthreads();
    const unsigned row = 0xFFFFFFFFu - (unsigned)(red64[0] & 0xFFFFFFFFull);
    const float* q = W + (size_t)row * VQ_DIM;

    // Copy winning row + commitment loss. 2 elems/thread.
    float q0 = q[tid];
    float q1 = q[tid + FIN_THREADS];
    if (tid < out_size) out[tid] = q0;
    if (tid + FIN_THREADS < out_size) out[tid + FIN_THREADS] = q1;
    float d0 = zv0 - q0, d1 = zv1 - q1;
    float s = d0 * d0 + d1 * d1;
    #pragma unroll
    for (int off = 16; off; off >>= 1)
        s += __shfl_xor_sync(0xffffffffu, s, off);
    if (lane == 0) redf[wwid] = s;
    __syncthreads();
    if (tid == 0) {
        float t = 0.f;
        #pragma unroll
        for (int i = 0; i < FIN_THREADS / 32; i++) t += redf[i];
        if (out_size >= VQ_DIM + 1) out[VQ_DIM]     = (float)row;
        if (out_size >= VQ_DIM + 2) out[VQ_DIM + 1] = 0.25f * t / (float)VQ_DIM;
    }
}

extern "C" void kernel_launch(void* const* d_in, const int* in_sizes, int n_in,
                              void* d_out, int out_size) {
    const float* z = (const float*)d_in[0];
    const float* W = (const float*)d_in[1];
    if (n_in >= 2 && in_sizes[0] != VQ_DIM && in_sizes[1] == VQ_DIM) {
        z = (const float*)d_in[1];
        W = (const float*)d_in[0];
    }
    float* out = (float*)d_out;

    cudaLaunchConfig_t cfg1 = {};
    cfg1.gridDim  = dim3(ARG_BLOCKS);
    cfg1.blockDim = dim3(ARG_THREADS);
    cudaLaunchKernelEx(&cfg1, vq_argmax_kernel, z, W);

    cudaLaunchConfig_t cfg2 = {};
    cfg2.gridDim  = dim3(1);
    cfg2.blockDim = dim3(FIN_THREADS);
    cudaLaunchAttribute attr;
    attr.id = cudaLaunchAttributeProgrammaticStreamSerialization;
    attr.val.programmaticStreamSerializationAllowed = 1;
    cfg2.attrs = &attr;
    cfg2.numAttrs = 1;
    cudaLaunchKernelEx(&cfg2, vq_finalize_kernel, z, W, out, out_size);
}

// round 7
// speedup vs baseline: 1.0341x; 1.0085x over previous
#include <cuda_runtime.h>

// VectorQuantizer: argmax_k ( W[k] . z ), emit W[argmax], index, commit loss.
// W: 131072 x 1024 f32 (512 MiB) -> pure HBM stream; floor ~65us @ 8 TB/s.
// R1's argmax config was the fastest measured (~70us, ~7.5 TB/s): grid 2048,
// launch_bounds(256,2) (NO tight reg cap -> ptxas schedules freely), two
// 4-deep load batches, plain loads. Reproduce it exactly; remove R1's waste
// (init kernel -> slot stores; finalize -> lean PDL kernel).

#define VQ_DIM   1024
#define VQ_ROWS  131072
#define ARG_BLOCKS  2048
#define ARG_THREADS 256
#define N_WARPS_TOT (ARG_BLOCKS * ARG_THREADS / 32)   // 16384 -> 8 rows/warp
#define FIN_THREADS 512

// Per-block packed (float_key(dot) << 32 | ~row). Overwritten every launch ->
// stale values from prior replays are harmless; no init pass needed.
__device__ unsigned long long g_block_best[ARG_BLOCKS];

// Monotonic float -> uint key: preserves ordering for all finite floats.
__device__ __forceinline__ unsigned float_key(float f) {
    unsigned u = __float_as_uint(f);
    return (u & 0x80000000u) ? ~u : (u | 0x80000000u);
}

__global__ __launch_bounds__(ARG_THREADS, 2)   // loose cap: ptxas freedom (R1)
void vq_argmax_kernel(const float* __restrict__ z, const float* __restrict__ W) {
    __shared__ float zs[VQ_DIM];
    __shared__ unsigned long long red64[ARG_THREADS / 32];

    const int tid  = threadIdx.x;
    const int lane = tid & 31;
    const int wwid = tid >> 5;

    // Stage z into shared (4 KB), vectorized.
    const float4* z4 = (const float4*)z;
    float4* zs4 = (float4*)zs;
    for (int i = tid; i < VQ_DIM / 4; i += ARG_THREADS)
        zs4[i] = z4[i];
    __syncthreads();

    const int gwarp = (blockIdx.x * ARG_THREADS + tid) >> 5;

    unsigned long long best = 0ULL;

    for (int row = gwarp; row < VQ_ROWS; row += N_WARPS_TOT) {
        const float4* wr = (const float4*)(W + (size_t)row * VQ_DIM);
        // R1 body: 4 accumulators, two 4-deep batches, full unroll.
        float a0 = 0.f, a1 = 0.f, a2 = 0.f, a3 = 0.f;
        #pragma unroll
        for (int it = 0; it < 8; it += 4) {
            float4 w0 = wr[lane + (it + 0) * 32];
            float4 w1 = wr[lane + (it + 1) * 32];
            float4 w2 = wr[lane + (it + 2) * 32];
            float4 w3 = wr[lane + (it + 3) * 32];
            float4 p0 = zs4[lane + (it + 0) * 32];
            float4 p1 = zs4[lane + (it + 1) * 32];
            float4 p2 = zs4[lane + (it + 2) * 32];
            float4 p3 = zs4[lane + (it + 3) * 32];
            a0 += w0.x * p0.x + w0.y * p0.y + w0.z * p0.z + w0.w * p0.w;
            a1 += w1.x * p1.x + w1.y * p1.y + w1.z * p1.z + w1.w * p1.w;
            a2 += w2.x * p2.x + w2.y * p2.y + w2.z * p2.z + w2.w * p2.w;
            a3 += w3.x * p3.x + w3.y * p3.y + w3.z * p3.z + w3.w * p3.w;
        }
        float dot = (a0 + a1) + (a2 + a3);

        #pragma unroll
        for (int off = 16; off; off >>= 1)
            dot += __shfl_xor_sync(0xffffffffu, dot, off);

        // ~row in low bits: ties resolve to SMALLEST row (jnp.argmax semantics).
        unsigned long long p =
            ((unsigned long long)float_key(dot) << 32) |
            (unsigned long long)(0xFFFFFFFFu - (unsigned)row);
        if (p > best) best = p;
    }

    // One value per warp -> 8-entry smem max -> slot store (no atomics).
    if (lane == 0) red64[wwid] = best;
    __syncthreads();
    if (tid == 0) {
        unsigned long long v = red64[0];
        #pragma unroll
        for (int i = 1; i < ARG_THREADS / 32; i++)
            if (red64[i] > v) v = red64[i];
        g_block_best[blockIdx.x] = v;
        __threadfence();
        asm volatile("griddepcontrol.launch_dependents;");
    }
}

__global__ __launch_bounds__(FIN_THREADS)
void vq_finalize_kernel(const float* __restrict__ z,
                        const float* __restrict__ W,
                        float* __restrict__ out, int out_size) {
    __shared__ unsigned long long red64[FIN_THREADS / 32];
    __shared__ float redf[FIN_THREADS / 32];
    const int tid  = threadIdx.x;
    const int lane = tid & 31;
    const int wwid = tid >> 5;

    // Prefetch z (independent of the primary) BEFORE the PDL wait.
    float zv0 = z[tid];
    float zv1 = z[tid + FIN_THREADS];

    asm volatile("griddepcontrol.wait;" ::: "memory");

    // Scan the 2048 slots, 4 per thread (L2-hot: just written by the primary).
    unsigned long long b = 0ULL;
    #pragma unroll
    for (int j = 0; j < ARG_BLOCKS / FIN_THREADS; j++) {
        unsigned long long v = g_block_best[tid + j * FIN_THREADS];
        if (v > b) b = v;
    }
    #pragma unroll
    for (int off = 16; off; off >>= 1) {
        unsigned long long o = __shfl_xor_sync(0xffffffffu, b, off);
        if (o > b) b = o;
    }
    if (lane == 0) red64[wwid] = b;
    __syncthreads();
    if (tid == 0) {
        unsigned long long v = red64[0];
        #pragma unroll
        for (int i = 1; i < FIN_THREADS / 32; i++)
            if (red64[i] > v) v = red64[i];
        red64[0] = v;
    }
    __syncthreads();
    const unsigned row = 0xFFFFFFFFu - (unsigned)(red64[0] & 0xFFFFFFFFull);
    const float* q = W + (size_t)row * VQ_DIM;

    // Copy winning row + commitment loss. 2 elems/thread.
    float q0 = q[tid];
    float q1 = q[tid + FIN_THREADS];
    if (tid < out_size) out[tid] = q0;
    if (tid + FIN_THREADS < out_size) out[tid + FIN_THREADS] = q1;
    float d0 = zv0 - q0, d1 = zv1 - q1;
    float s = d0 * d0 + d1 * d1;
    #pragma unroll
    for (int off = 16; off; off >>= 1)
        s += __shfl_xor_sync(0xffffffffu, s, off);
    if (lane == 0) redf[wwid] = s;
    __syncthreads();
    if (tid == 0) {
        float t = 0.f;
        #pragma unroll
        for (int i = 0; i < FIN_THREADS / 32; i++) t += redf[i];
        if (out_size >= VQ_DIM + 1) out[VQ_DIM]     = (float)row;
        if (out_size >= VQ_DIM + 2) out[VQ_DIM + 1] = 0.25f * t / (float)VQ_DIM;
    }
}

extern "C" void kernel_launch(void* const* d_in, const int* in_sizes, int n_in,
                              void* d_out, int out_size) {
    const float* z = (const float*)d_in[0];
    const float* W = (const float*)d_in[1];
    if (n_in >= 2 && in_sizes[0] != VQ_DIM && in_sizes[1] == VQ_DIM) {
        z = (const float*)d_in[1];
        W = (const float*)d_in[0];
    }
    float* out = (float*)d_out;

    cudaLaunchConfig_t cfg1 = {};
    cfg1.gridDim  = dim3(ARG_BLOCKS);
    cfg1.blockDim = dim3(ARG_THREADS);
    cudaLaunchKernelEx(&cfg1, vq_argmax_kernel, z, W);

    cudaLaunchConfig_t cfg2 = {};
    cfg2.gridDim  = dim3(1);
    cfg2.blockDim = dim3(FIN_THREADS);
    cudaLaunchAttribute attr;
    attr.id = cudaLaunchAttributeProgrammaticStreamSerialization;
    attr.val.programmaticStreamSerializationAllowed = 1;
    cfg2.attrs = &attr;
    cfg2.numAttrs = 1;
    cudaLaunchKernelEx(&cfg2, vq_finalize_kernel, z, W, out, out_size);
}